// round 15
// baseline (speedup 1.0000x reference)
#include <cuda_runtime.h>
#include <math.h>

#define WNB   64
#define LSEQ  512
#define CM    96
#define DI    192
#define DS    16
#define E2    384
#define NPOS  (WNB*LSEQ)   // 32768
#define NSPAT 32768

// ---------------- scratch ----------------------------------------------------
__device__ __align__(16) float g_xn[NPOS*CM];
__device__ __align__(16) float g_xz[NPOS*E2];
__device__ __align__(16) float g_u[3][NPOS*DI];
__device__ __align__(16) float g_dt[3][NPOS*6];
__device__ __align__(16) float g_delta[3][NPOS*DI];
__device__ __align__(16) float g_Bm[3][NPOS*DS];
__device__ __align__(16) float g_Cm[3][NPOS*DS];
__device__ __align__(16) float g_y[3][NPOS*DI];
__device__ float g_mean[CM];
__device__ float g_gate[CM];

__device__ __forceinline__ float siluf(float v){ return v / (1.f + __expf(-v)); }
__device__ __forceinline__ float softplusf(float v){ return v > 15.f ? v : __logf(1.f + __expf(v)); }

typedef unsigned long long ull;
__device__ __forceinline__ ull fma2(ull a, ull b, ull c){
    ull d; asm("fma.rn.f32x2 %0, %1, %2, %3;" : "=l"(d) : "l"(a), "l"(b), "l"(c)); return d;
}
__device__ __forceinline__ ull mul2(ull a, ull b){
    ull d; asm("mul.rn.f32x2 %0, %1, %2;" : "=l"(d) : "l"(a), "l"(b)); return d;
}
__device__ __forceinline__ ull pack2(float lo, float hi){
    ull d; asm("mov.b64 %0, {%1, %2};" : "=l"(d) : "f"(lo), "f"(hi)); return d;
}
__device__ __forceinline__ float2 unpack2(ull v){
    float2 r; asm("mov.b64 {%0, %1}, %2;" : "=f"(r.x), "=f"(r.y) : "l"(v)); return r;
}
__device__ __forceinline__ ull splat2(float v){ return pack2(v, v); }

__device__ __forceinline__ int perm_idx(int br, int t){
    if (br == 0) return t;
    if (br == 1) return 511 - t;
    return ((t & 7) << 6) + (t >> 3);
}

// ---------------- K1: layernorm + window gather -------------------------------
__global__ void ln_kernel(const float* __restrict__ x,
                          const float* __restrict__ lnw,
                          const float* __restrict__ lnb){
    extern __shared__ float tile[];            // [96][129]
    __shared__ float s_mu[128], s_rs[128];
    __shared__ int   s_m[128];
    __shared__ float s_w[96], s_b[96];
    int tid = threadIdx.x;                     // 128
    int s0  = blockIdx.x * 128;
    if (tid < 96){ s_w[tid] = lnw[tid]; s_b[tid] = lnb[tid]; }
    int s = s0 + tid;
    float sum = 0.f, sq = 0.f;
    #pragma unroll 4
    for (int c = 0; c < 96; c++){
        float v = x[c*NSPAT + s];
        tile[c*129 + tid] = v;
        sum += v; sq = fmaf(v, v, sq);
    }
    float mu  = sum * (1.f/96);
    float var = sq  * (1.f/96) - mu*mu;
    s_mu[tid] = mu;
    s_rs[tid] = rsqrtf(var + 1e-5f);
    int h = s >> 10, w = (s >> 5) & 31, dd = s & 31;
    int b = (h>>3)*16 + (w>>3)*4 + (dd>>3);
    int l = (h&7)*64 + (w&7)*8 + (dd&7);
    s_m[tid] = b*LSEQ + l;
    __syncthreads();
    #pragma unroll 4
    for (int i = 0; i < 96; i++){
        int f = i*128 + tid;
        int c = f % 96, r = f / 96;
        float v = tile[c*129 + r];
        g_xn[s_m[r]*96 + c] = (v - s_mu[r])*s_rs[r]*s_w[c] + s_b[c];
    }
}

// ---------------- K2: in_proj GEMM (f32x2, 4m x 8n, 64x128 tiles) -------------
#define INP_SMEM ((48*92 + 48*184)*4)   // 52992 B
__global__ void __launch_bounds__(256)
inproj_kernel(const float* __restrict__ W){
    extern __shared__ float smi[];
    float* As = smi;              // [48][92]
    float* Ws = smi + 48*92;      // [48][184]
    int tid = threadIdx.x;        // 256
    int m0 = blockIdx.x * 64;
    int n0 = blockIdx.y * 128;
    ull acc2[4][4];
    #pragma unroll
    for (int i = 0; i < 4; i++)
        #pragma unroll
        for (int j = 0; j < 4; j++) acc2[i][j] = 0ull;
    int lr = tid & 15;        // 4 m rows each
    int nr = tid >> 4;        // 0..15, 8 n each (4 pairs)
    for (int kk = 0; kk < 96; kk += 48){
        __syncthreads();
        for (int f = tid; f < 768; f += 256){
            int row = f / 12, kq = f % 12;
            int sw = 4*(kq & 7);
            float4 a = *(const float4*)&g_xn[(m0+row)*96 + kk + kq*4];
            As[(kq*4+0)*92 + row + sw] = a.x; As[(kq*4+1)*92 + row + sw] = a.y;
            As[(kq*4+2)*92 + row + sw] = a.z; As[(kq*4+3)*92 + row + sw] = a.w;
        }
        for (int f = tid; f < 1536; f += 256){
            int row = f / 12, kq = f % 12;
            int sw = 4*(kq & 7);
            float4 bvec = *(const float4*)&W[(n0+row)*96 + kk + kq*4];
            Ws[(kq*4+0)*184 + row + sw] = bvec.x; Ws[(kq*4+1)*184 + row + sw] = bvec.y;
            Ws[(kq*4+2)*184 + row + sw] = bvec.z; Ws[(kq*4+3)*184 + row + sw] = bvec.w;
        }
        __syncthreads();
        #pragma unroll 4
        for (int k = 0; k < 48; k++){
            int sw = 4*((k>>2) & 7);
            float4 a  = *(const float4*)&As[k*92 + 4*lr + sw];
            float4 b0 = *(const float4*)&Ws[k*184 + 8*nr + sw];
            float4 b1 = *(const float4*)&Ws[k*184 + 8*nr + 4 + sw];
            ull bu[4] = { pack2(b0.x, b0.y), pack2(b0.z, b0.w),
                          pack2(b1.x, b1.y), pack2(b1.z, b1.w) };
            ull pa[4] = { splat2(a.x), splat2(a.y), splat2(a.z), splat2(a.w) };
            #pragma unroll
            for (int i = 0; i < 4; i++)
                #pragma unroll
                for (int j = 0; j < 4; j++)
                    acc2[i][j] = fma2(pa[i], bu[j], acc2[i][j]);
        }
    }
    #pragma unroll
    for (int i = 0; i < 4; i++){
        float2 p0 = unpack2(acc2[i][0]), p1 = unpack2(acc2[i][1]);
        float2 p2 = unpack2(acc2[i][2]), p3 = unpack2(acc2[i][3]);
        float* dst = &g_xz[(size_t)(m0 + 4*lr + i)*E2 + n0 + 8*nr];
        *(float4*)dst       = make_float4(p0.x, p0.y, p1.x, p1.y);
        *(float4*)(dst + 4) = make_float4(p2.x, p2.y, p3.x, p3.y);
    }
}

// ---------------- K3: causal conv4 + SiLU (4 t-chunks of 128) -----------------
__global__ void conv_kernel(const float* __restrict__ cw0, const float* __restrict__ cb0,
                            const float* __restrict__ cw1, const float* __restrict__ cb1,
                            const float* __restrict__ cw2, const float* __restrict__ cb2){
    int d   = threadIdx.x;            // 0..191
    int tc  = blockIdx.x;             // 0..3
    int b   = blockIdx.y;             // 0..63
    int br  = blockIdx.z;             // 0..2
    const float* cw = (br == 0) ? cw0 : (br == 1) ? cw1 : cw2;
    const float* cb = (br == 0) ? cb0 : (br == 1) ? cb1 : cb2;
    float w0 = cw[d*4+0], w1 = cw[d*4+1], w2 = cw[d*4+2], w3 = cw[d*4+3];
    float bias = cb[d];
    const float* xb = g_xz + (size_t)b*LSEQ*E2 + d;
    float* ub = g_u[br] + (size_t)(b*LSEQ)*DI + d;
    int t0 = tc*128;
    float x1 = 0.f, x2 = 0.f, x3 = 0.f;
    if (t0 >= 1) x1 = xb[perm_idx(br, t0-1)*E2];
    if (t0 >= 2) x2 = xb[perm_idx(br, t0-2)*E2];
    if (t0 >= 3) x3 = xb[perm_idx(br, t0-3)*E2];
    float pf[8];
    #pragma unroll
    for (int j = 0; j < 8; j++) pf[j] = xb[perm_idx(br, t0+j)*E2];
    #pragma unroll 8
    for (int i = 0; i < 128; i++){
        int t = t0 + i;
        float xv = pf[i & 7];
        int tn = t + 8;
        if (tn < (tc+1)*128 + 8 && tn < LSEQ) pf[i & 7] = xb[perm_idx(br, tn)*E2];
        float acc = bias;
        acc = fmaf(w0, x3, acc);
        acc = fmaf(w1, x2, acc);
        acc = fmaf(w2, x1, acc);
        acc = fmaf(w3, xv, acc);
        ub[t*DI] = siluf(acc);
        x3 = x2; x2 = x1; x1 = xv;
    }
}

// ---------------- K4: x_dbl GEMM + dt/B/C out (f32x2, 8m x 10r, M-tile 256) ---
#define XDBL_SMEM ((2880 + 32*316)*4)   // 51968 B
__global__ void xdbl_kernel(const float* __restrict__ xp0,
                            const float* __restrict__ xp1,
                            const float* __restrict__ xp2){
    extern __shared__ float sm[];
    float* ws2 = sm;                  // float2[32][45]
    float* us  = sm + 2880;           // [32][316]
    float* xds = sm;                  // overlay [256][41]
    int tid = threadIdx.x;            // 128
    int br  = blockIdx.y;
    int m0  = blockIdx.x * 256;
    const float* xpw = (br == 0) ? xp0 : (br == 1) ? xp1 : xp2;
    const float* gu = g_u[br];
    int mg = tid & 31;      // 8 m rows (4 pairs)
    int rg = tid >> 5;      // 10 r cols (0..3)
    ull acc2[4][10];
    #pragma unroll
    for (int i = 0; i < 4; i++)
        #pragma unroll
        for (int j = 0; j < 10; j++) acc2[i][j] = 0ull;
    for (int kk = 0; kk < 192; kk += 32){
        __syncthreads();
        for (int f = tid; f < 304; f += 128){
            int r = f >> 3, k4 = f & 7;
            float4 v = *(const float4*)&xpw[r*192 + kk + 4*k4];
            *(ull*)&ws2[((4*k4+0)*45 + r)*2] = pack2(v.x, v.x);
            *(ull*)&ws2[((4*k4+1)*45 + r)*2] = pack2(v.y, v.y);
            *(ull*)&ws2[((4*k4+2)*45 + r)*2] = pack2(v.z, v.z);
            *(ull*)&ws2[((4*k4+3)*45 + r)*2] = pack2(v.w, v.w);
        }
        for (int f = tid; f < 224; f += 128){
            int k = f / 7, r = 38 + f % 7;
            *(ull*)&ws2[(k*45 + r)*2] = 0ull;
        }
        for (int f = tid; f < 2048; f += 128){
            int m = f >> 3, k4 = f & 7;
            float4 v = *(const float4*)&gu[(size_t)(m0+m)*192 + kk + 4*k4];
            int col = m + 4*k4 + 4*((m >> 5) & 7);
            us[(4*k4+0)*316 + col] = v.x;
            us[(4*k4+1)*316 + col] = v.y;
            us[(4*k4+2)*316 + col] = v.z;
            us[(4*k4+3)*316 + col] = v.w;
        }
        __syncthreads();
        #pragma unroll 4
        for (int k = 0; k < 32; k++){
            int ac = 8*mg + 4*((mg>>2) & 7) + 4*(k >> 2);
            float4 a0 = *(const float4*)&us[k*316 + ac];
            float4 a1 = *(const float4*)&us[k*316 + ac + 4];
            ull au[4] = { pack2(a0.x, a0.y), pack2(a0.z, a0.w),
                          pack2(a1.x, a1.y), pack2(a1.z, a1.w) };
            const ull* wp = (const ull*)&ws2[k*90];
            #pragma unroll
            for (int j = 0; j < 10; j++){
                ull wv = wp[10*rg + j];
                #pragma unroll
                for (int i = 0; i < 4; i++)
                    acc2[i][j] = fma2(au[i], wv, acc2[i][j]);
            }
        }
    }
    __syncthreads();
    #pragma unroll
    for (int i = 0; i < 4; i++)
        #pragma unroll
        for (int j = 0; j < 10; j++){
            float2 p = unpack2(acc2[i][j]);
            xds[(8*mg + 2*i    )*41 + 10*rg + j] = p.x;
            xds[(8*mg + 2*i + 1)*41 + 10*rg + j] = p.y;
        }
    __syncthreads();
    {
        float* gdt = g_dt[br] + (size_t)m0*6;
        for (int f = tid; f < 1536; f += 128){
            int m = f / 6, r = f % 6;
            gdt[f] = xds[m*41 + r];
        }
    }
    float* gB = g_Bm[br];
    float* gC = g_Cm[br];
    for (int f = tid; f < 8192; f += 128){
        int m = f >> 5, j = f & 31;
        float v = xds[m*41 + 6 + j];
        if (j < 16) gB[(size_t)(m0+m)*DS + j]      = v;
        else        gC[(size_t)(m0+m)*DS + (j-16)] = v;
    }
}

// ---------------- K4b: delta kernel (streaming, high occupancy) ---------------
__global__ void delta_kernel(const float* __restrict__ dw0, const float* __restrict__ db0,
                             const float* __restrict__ dw1, const float* __restrict__ db1,
                             const float* __restrict__ dw2, const float* __restrict__ db2){
    __shared__ float sdt[64*6];
    int d  = threadIdx.x;             // 192
    int br = blockIdx.y;
    int m0 = blockIdx.x * 64;
    const float* dtw = (br == 0) ? dw0 : (br == 1) ? dw1 : dw2;
    const float* dtb = (br == 0) ? db0 : (br == 1) ? db1 : db2;
    {
        const float* src = g_dt[br] + (size_t)m0*6;
        for (int f = d; f < 384; f += 192) sdt[f] = src[f];
    }
    float dwr[6];
    #pragma unroll
    for (int r = 0; r < 6; r++) dwr[r] = dtw[d*6 + r];
    float db_ = dtb[d];
    float* gD = g_delta[br] + (size_t)m0*DI + d;
    __syncthreads();
    #pragma unroll 4
    for (int m = 0; m < 64; m++){
        float acc = db_;
        #pragma unroll
        for (int r = 0; r < 6; r++)
            acc = fmaf(sdt[m*6 + r], dwr[r], acc);
        gD[m*DI] = softplusf(acc);
    }
}

// ---------------- K5: selective scan (chunked smem, f32x2 power tree) ---------
__global__ void scan_kernel(const float* __restrict__ Al0, const float* __restrict__ Dp0,
                            const float* __restrict__ Al1, const float* __restrict__ Dp1,
                            const float* __restrict__ Al2, const float* __restrict__ Dp2){
    __shared__ float sd[16*96];
    __shared__ float su[16*96];
    __shared__ __align__(16) float sB[16*16];
    __shared__ __align__(16) float sC[16*16];
    int tid  = threadIdx.x;           // 0..95
    int b    = blockIdx.x;
    int half = blockIdx.y;
    int br   = blockIdx.z;
    int d    = half*96 + tid;
    const float* Alog = (br == 0) ? Al0 : (br == 1) ? Al1 : Al2;
    const float* Dp   = (br == 0) ? Dp0 : (br == 1) ? Dp1 : Dp2;
    float Ar[16];
    #pragma unroll
    for (int s = 0; s < 16; s++) Ar[s] = -__expf(Alog[d*16 + s]);
    bool fast = true;
    #pragma unroll
    for (int s = 0; s < 16; s++)
        fast = fast && (fabsf(Ar[s] + (float)(s+1)) < 1e-3f*(float)(s+1));
    float Ar0 = Ar[0];
    float Dd = Dp[d];
    ull h2[8];
    #pragma unroll
    for (int s = 0; s < 8; s++) h2[s] = 0ull;
    float hs[16];
    #pragma unroll
    for (int s = 0; s < 16; s++) hs[s] = 0.f;
    const float* gdp = g_delta[br] + (size_t)(b*LSEQ)*DI + d;
    const float* gup = g_u[br]     + (size_t)(b*LSEQ)*DI + d;
    const float* gBp = g_Bm[br]    + (size_t)(b*LSEQ)*DS;
    const float* gCp = g_Cm[br]    + (size_t)(b*LSEQ)*DS;
    float* yb = g_y[br] + (size_t)(b*LSEQ)*DI + d;
    float pd[16], pu[16], pb[3], pc[3];
    #pragma unroll
    for (int i = 0; i < 16; i++){ pd[i] = gdp[i*DI]; pu[i] = gup[i*DI]; }
    #pragma unroll
    for (int i = 0; i < 3; i++){
        int idx = i*96 + tid;
        pb[i] = (idx < 256) ? gBp[idx] : 0.f;
        pc[i] = (idx < 256) ? gCp[idx] : 0.f;
    }
    for (int c = 0; c < 32; c++){
        #pragma unroll
        for (int i = 0; i < 16; i++){ sd[i*96+tid] = pd[i]; su[i*96+tid] = pu[i]; }
        #pragma unroll
        for (int i = 0; i < 3; i++){
            int idx = i*96 + tid;
            if (idx < 256){ sB[idx] = pb[i]; sC[idx] = pc[i]; }
        }
        __syncthreads();
        if (c + 1 < 32){
            size_t ofs = (size_t)(c+1)*16*DI;
            #pragma unroll
            for (int i = 0; i < 16; i++){ pd[i] = gdp[ofs + i*DI]; pu[i] = gup[ofs + i*DI]; }
            int ofb = (c+1)*256;
            #pragma unroll
            for (int i = 0; i < 3; i++){
                int idx = i*96 + tid;
                if (idx < 256){ pb[i] = gBp[ofb + idx]; pc[i] = gCp[ofb + idx]; }
            }
        }
        if (fast){
            for (int t2 = 0; t2 < 16; t2++){
                float delta = sd[t2*96 + tid];
                float u     = su[t2*96 + tid];
                float du    = delta * u;
                float q  = __expf(delta * Ar0);
                float q2 = q*q;
                ull v0 = pack2(q, q2);
                ull s2 = pack2(q2, q2);
                ull v1 = mul2(v0, s2);
                float q4 = unpack2(v1).y;
                ull s4 = pack2(q4, q4);
                ull v2 = mul2(v0, s4);
                ull v3 = mul2(v1, s4);
                float q8 = unpack2(v3).y;
                ull s8 = pack2(q8, q8);
                ull pw[8] = {v0, v1, v2, v3,
                             mul2(v0, s8), mul2(v1, s8), mul2(v2, s8), mul2(v3, s8)};
                ull du2 = pack2(du, du);
                const ulonglong2* B2 = (const ulonglong2*)(sB + t2*16);
                const ulonglong2* C2 = (const ulonglong2*)(sC + t2*16);
                ull y2 = 0ull;
                #pragma unroll
                for (int i = 0; i < 4; i++){
                    ulonglong2 Bv = B2[i];
                    ulonglong2 Cv = C2[i];
                    h2[2*i]   = fma2(h2[2*i],   pw[2*i],   mul2(Bv.x, du2));
                    y2 = fma2(h2[2*i], Cv.x, y2);
                    h2[2*i+1] = fma2(h2[2*i+1], pw[2*i+1], mul2(Bv.y, du2));
                    y2 = fma2(h2[2*i+1], Cv.y, y2);
                }
                float2 yy = unpack2(y2);
                int t = c*16 + t2;
                yb[perm_idx(br, t)*DI] = fmaf(Dd, u, yy.x + yy.y);
            }
        } else {
            for (int t2 = 0; t2 < 16; t2++){
                float delta = sd[t2*96 + tid];
                float u     = su[t2*96 + tid];
                float du    = delta * u;
                float y = 0.f;
                #pragma unroll
                for (int s = 0; s < 16; s++){
                    float dA = __expf(delta * Ar[s]);
                    hs[s] = fmaf(hs[s], dA, du * sB[t2*16 + s]);
                    y     = fmaf(hs[s], sC[t2*16 + s], y);
                }
                int t = c*16 + t2;
                yb[perm_idx(br, t)*DI] = fmaf(Dd, u, y);
            }
        }
        __syncthreads();
    }
}

// ---------------- K6: combine*silu(z) + out_proj (f32x2) + reverse + residual -
#define OUTP_SMEM ((32*92 + 32*124)*4)    // 27648 B (>= Cs 25600)
__global__ void outproj_kernel(const float* __restrict__ W,
                               const float* __restrict__ x,
                               float* __restrict__ out){
    extern __shared__ float sm2[];
    float* As  = sm2;                 // [32][92]
    float* Ws2 = sm2 + 32*92;         // [32][124]
    float* Cs  = sm2;                 // epilogue overlay [64][100]
    int tid = threadIdx.x;            // 128
    int m0 = blockIdx.x * 64;
    int mg = tid & 15;
    int ng = tid >> 4;
    ull acc2[4][6];
    #pragma unroll
    for (int i = 0; i < 4; i++)
        #pragma unroll
        for (int j = 0; j < 6; j++) acc2[i][j] = 0ull;
    for (int kk = 0; kk < 192; kk += 32){
        __syncthreads();
        for (int f = tid; f < 512; f += 128){
            int m = f >> 3, k4 = f & 7;
            size_t mi = (size_t)(m0+m)*DI + kk + 4*k4;
            float4 y0 = *(const float4*)&g_y[0][mi];
            float4 y1 = *(const float4*)&g_y[1][mi];
            float4 y2 = *(const float4*)&g_y[2][mi];
            float4 z  = *(const float4*)&g_xz[(size_t)(m0+m)*E2 + DI + kk + 4*k4];
            int col = m + 4*k4;
            As[(4*k4+0)*92 + col] = (y0.x+y1.x+y2.x)*siluf(z.x);
            As[(4*k4+1)*92 + col] = (y0.y+y1.y+y2.y)*siluf(z.y);
            As[(4*k4+2)*92 + col] = (y0.z+y1.z+y2.z)*siluf(z.z);
            As[(4*k4+3)*92 + col] = (y0.w+y1.w+y2.w)*siluf(z.w);
        }
        for (int f = tid; f < 768; f += 128){
            int cc = f >> 3, k4 = f & 7;
            float4 wv = *(const float4*)&W[cc*DI + kk + 4*k4];
            int col = cc + 4*k4;
            Ws2[(4*k4+0)*124 + col] = wv.x;
            Ws2[(4*k4+1)*124 + col] = wv.y;
            Ws2[(4*k4+2)*124 + col] = wv.z;
            Ws2[(4*k4+3)*124 + col] = wv.w;
        }
        __syncthreads();
        #pragma unroll 4
        for (int k = 0; k < 32; k++){
            int sw = 4*(k >> 2);
            float4 a = *(const float4*)&As[k*92 + 4*mg + sw];
            ull pa[4] = { splat2(a.x), splat2(a.y), splat2(a.z), splat2(a.w) };
            float4 b0 = *(const float4*)&Ws2[k*124 + 12*ng + sw];
            float4 b1 = *(const float4*)&Ws2[k*124 + 12*ng + 4 + sw];
            float4 b2 = *(const float4*)&Ws2[k*124 + 12*ng + 8 + sw];
            ull bu[6] = { pack2(b0.x,b0.y), pack2(b0.z,b0.w),
                          pack2(b1.x,b1.y), pack2(b1.z,b1.w),
                          pack2(b2.x,b2.y), pack2(b2.z,b2.w) };
            #pragma unroll
            for (int i = 0; i < 4; i++)
                #pragma unroll
                for (int j = 0; j < 6; j++)
                    acc2[i][j] = fma2(pa[i], bu[j], acc2[i][j]);
        }
    }
    __syncthreads();
    #pragma unroll
    for (int i = 0; i < 4; i++){
        float2 p0 = unpack2(acc2[i][0]), p1 = unpack2(acc2[i][1]);
        float2 p2 = unpack2(acc2[i][2]), p3 = unpack2(acc2[i][3]);
        float2 p4 = unpack2(acc2[i][4]), p5 = unpack2(acc2[i][5]);
        float* dst = &Cs[(4*mg+i)*100 + 12*ng];
        *(float4*)(dst    ) = make_float4(p0.x, p0.y, p1.x, p1.y);
        *(float4*)(dst + 4) = make_float4(p2.x, p2.y, p3.x, p3.y);
        *(float4*)(dst + 8) = make_float4(p4.x, p4.y, p5.x, p5.y);
    }
    __syncthreads();
    for (int f = tid; f < 64*96; f += 128){
        int cc = f >> 6, m = f & 63;
        int M = m0 + m;
        int b = M >> 9, l = M & 511;
        int hb = b >> 4, wb = (b >> 2) & 3, db = b & 3;
        int lh = l >> 6, lw = (l >> 3) & 7, ld = l & 7;
        int sp = (hb*8+lh)*1024 + (wb*8+lw)*32 + (db*8+ld);
        int oi = cc*NSPAT + sp;
        out[oi] = Cs[m*100 + cc] + x[oi];
    }
}

// ---------------- K7/K8/K9: ECA ----------------------------------------------
__global__ void mean_kernel(const float* __restrict__ out){
    __shared__ float red[256];
    int c = blockIdx.x;
    const float4* p = (const float4*)(out + (size_t)c*NSPAT);
    float s = 0.f;
    for (int i = threadIdx.x; i < NSPAT/4; i += 256){
        float4 v = p[i];
        s += (v.x + v.y) + (v.z + v.w);
    }
    red[threadIdx.x] = s; __syncthreads();
    for (int st = 128; st > 0; st >>= 1){
        if (threadIdx.x < st) red[threadIdx.x] += red[threadIdx.x + st];
        __syncthreads();
    }
    if (threadIdx.x == 0) g_mean[c] = red[0] * (1.f/NSPAT);
}

__global__ void gate_kernel(const float* __restrict__ ew){
    int c = threadIdx.x;
    if (c < CM){
        float m0 = (c > 0)    ? g_mean[c-1] : 0.f;
        float m1 = g_mean[c];
        float m2 = (c < CM-1) ? g_mean[c+1] : 0.f;
        float v = ew[0]*m0 + ew[1]*m1 + ew[2]*m2;
        g_gate[c] = 1.f / (1.f + __expf(-v));
    }
}

__global__ void scale_kernel(float* __restrict__ out){
    int i = blockIdx.x*256 + threadIdx.x;
    float g = g_gate[i >> 13];
    float4* p = (float4*)out;
    float4 v = p[i];
    v.x *= g; v.y *= g; v.z *= g; v.w *= g;
    p[i] = v;
}

// -----------------------------------------------------------------------------
extern "C" void kernel_launch(void* const* d_in, const int* in_sizes, int n_in,
                              void* d_out, int out_size){
    const float* x   = (const float*)d_in[0];
    const float* lnw = (const float*)d_in[1];
    const float* lnb = (const float*)d_in[2];
    const float* ipw = (const float*)d_in[3];
    const float* opw = (const float*)d_in[4];
    int base, eca_idx;
    if (in_sizes[5] == 3) { eca_idx = 5;  base = 6; }
    else                  { base = 5;     eca_idx = 26; }
    const float* ecw = (const float*)d_in[eca_idx];
    const float *cw[3], *cb[3], *xp[3], *dw[3], *db[3], *Al[3], *Dp[3];
    for (int br = 0; br < 3; br++){
        const int o = base + 7*br;
        cw[br] = (const float*)d_in[o+0];
        cb[br] = (const float*)d_in[o+1];
        xp[br] = (const float*)d_in[o+2];
        dw[br] = (const float*)d_in[o+3];
        db[br] = (const float*)d_in[o+4];
        Al[br] = (const float*)d_in[o+5];
        Dp[br] = (const float*)d_in[o+6];
    }
    float* out = (float*)d_out;

    cudaFuncSetAttribute(ln_kernel,      cudaFuncAttributeMaxDynamicSharedMemorySize, 96*129*4);
    cudaFuncSetAttribute(inproj_kernel,  cudaFuncAttributeMaxDynamicSharedMemorySize, INP_SMEM);
    cudaFuncSetAttribute(xdbl_kernel,    cudaFuncAttributeMaxDynamicSharedMemorySize, XDBL_SMEM);
    cudaFuncSetAttribute(outproj_kernel, cudaFuncAttributeMaxDynamicSharedMemorySize, OUTP_SMEM);

    ln_kernel<<<NSPAT/128, 128, 96*129*4>>>(x, lnw, lnb);
    { dim3 g(NPOS/64, E2/128); inproj_kernel<<<g, 256, INP_SMEM>>>(ipw); }
    { dim3 g(4, WNB, 3); conv_kernel<<<g, DI>>>(cw[0],cb[0],cw[1],cb[1],cw[2],cb[2]); }
    { dim3 g(NPOS/256, 3); xdbl_kernel<<<g, 128, XDBL_SMEM>>>(xp[0], xp[1], xp[2]); }
    { dim3 g(NPOS/64, 3);  delta_kernel<<<g, 192>>>(dw[0],db[0],dw[1],db[1],dw[2],db[2]); }
    { dim3 g(WNB, 2, 3); scan_kernel<<<g, 96>>>(Al[0],Dp[0],Al[1],Dp[1],Al[2],Dp[2]); }
    outproj_kernel<<<NPOS/64, 128, OUTP_SMEM>>>(opw, x, out);
    mean_kernel<<<CM, 256>>>(out);
    gate_kernel<<<1, 128>>>(ecw);
    scale_kernel<<<(CM*NSPAT/4)/256, 256>>>(out);
    (void)n_in; (void)out_size;
}

// round 16
// speedup vs baseline: 1.0264x; 1.0264x over previous
#include <cuda_runtime.h>
#include <math.h>

#define WNB   64
#define LSEQ  512
#define CM    96
#define DI    192
#define DS    16
#define E2    384
#define NPOS  (WNB*LSEQ)   // 32768
#define NSPAT 32768

// ---------------- scratch ----------------------------------------------------
__device__ __align__(16) float g_xn[NPOS*CM];
__device__ __align__(16) float g_xz[NPOS*E2];
__device__ __align__(16) float g_u[3][NPOS*DI];
__device__ __align__(16) float g_dt[3][NPOS*6];
__device__ __align__(16) float g_delta[3][NPOS*DI];
__device__ __align__(16) float g_Bm[3][NPOS*DS];
__device__ __align__(16) float g_Cm[3][NPOS*DS];
__device__ __align__(16) float g_y[3][NPOS*DI];
__device__ float g_mean[CM];
__device__ float g_gate[CM];

__device__ __forceinline__ float siluf(float v){ return v / (1.f + __expf(-v)); }
__device__ __forceinline__ float softplusf(float v){ return v > 15.f ? v : __logf(1.f + __expf(v)); }

typedef unsigned long long ull;
__device__ __forceinline__ ull fma2(ull a, ull b, ull c){
    ull d; asm("fma.rn.f32x2 %0, %1, %2, %3;" : "=l"(d) : "l"(a), "l"(b), "l"(c)); return d;
}
__device__ __forceinline__ ull mul2(ull a, ull b){
    ull d; asm("mul.rn.f32x2 %0, %1, %2;" : "=l"(d) : "l"(a), "l"(b)); return d;
}
__device__ __forceinline__ ull pack2(float lo, float hi){
    ull d; asm("mov.b64 %0, {%1, %2};" : "=l"(d) : "f"(lo), "f"(hi)); return d;
}
__device__ __forceinline__ float2 unpack2(ull v){
    float2 r; asm("mov.b64 {%0, %1}, %2;" : "=f"(r.x), "=f"(r.y) : "l"(v)); return r;
}
__device__ __forceinline__ ull splat2(float v){ return pack2(v, v); }

__device__ __forceinline__ int perm_idx(int br, int t){
    if (br == 0) return t;
    if (br == 1) return 511 - t;
    return ((t & 7) << 6) + (t >> 3);
}

// ---------------- K1: layernorm + window gather -------------------------------
__global__ void ln_kernel(const float* __restrict__ x,
                          const float* __restrict__ lnw,
                          const float* __restrict__ lnb){
    extern __shared__ float tile[];            // [96][129]
    __shared__ float s_mu[128], s_rs[128];
    __shared__ int   s_m[128];
    __shared__ float s_w[96], s_b[96];
    int tid = threadIdx.x;                     // 128
    int s0  = blockIdx.x * 128;
    if (tid < 96){ s_w[tid] = lnw[tid]; s_b[tid] = lnb[tid]; }
    int s = s0 + tid;
    float sum = 0.f, sq = 0.f;
    #pragma unroll 4
    for (int c = 0; c < 96; c++){
        float v = x[c*NSPAT + s];
        tile[c*129 + tid] = v;
        sum += v; sq = fmaf(v, v, sq);
    }
    float mu  = sum * (1.f/96);
    float var = sq  * (1.f/96) - mu*mu;
    s_mu[tid] = mu;
    s_rs[tid] = rsqrtf(var + 1e-5f);
    int h = s >> 10, w = (s >> 5) & 31, dd = s & 31;
    int b = (h>>3)*16 + (w>>3)*4 + (dd>>3);
    int l = (h&7)*64 + (w&7)*8 + (dd&7);
    s_m[tid] = b*LSEQ + l;
    __syncthreads();
    #pragma unroll 4
    for (int i = 0; i < 96; i++){
        int f = i*128 + tid;
        int c = f % 96, r = f / 96;
        float v = tile[c*129 + r];
        g_xn[s_m[r]*96 + c] = (v - s_mu[r])*s_rs[r]*s_w[c] + s_b[c];
    }
}

// ---------------- K2: in_proj GEMM (f32x2, 4m x 8n, 64x64 tiles) --------------
__global__ void inproj_kernel(const float* __restrict__ W){
    __shared__ float As[48*92];
    __shared__ float Ws[48*92];
    int tid = threadIdx.x;            // 128
    int m0 = blockIdx.x * 64;
    int n0 = blockIdx.y * 64;
    ull acc2[4][4];
    #pragma unroll
    for (int i = 0; i < 4; i++)
        #pragma unroll
        for (int j = 0; j < 4; j++) acc2[i][j] = 0ull;
    int lr = tid & 15;
    int nr = tid >> 4;
    for (int kk = 0; kk < 96; kk += 48){
        __syncthreads();
        #pragma unroll
        for (int j = 0; j < 6; j++){
            int f = tid + j*128;
            int row = f / 12, kq = f % 12;
            int sw = 4*(kq & 7);
            float4 a = *(const float4*)&g_xn[(m0+row)*96 + kk + kq*4];
            As[(kq*4+0)*92 + row + sw] = a.x; As[(kq*4+1)*92 + row + sw] = a.y;
            As[(kq*4+2)*92 + row + sw] = a.z; As[(kq*4+3)*92 + row + sw] = a.w;
            float4 bvec = *(const float4*)&W[(n0+row)*96 + kk + kq*4];
            Ws[(kq*4+0)*92 + row + sw] = bvec.x; Ws[(kq*4+1)*92 + row + sw] = bvec.y;
            Ws[(kq*4+2)*92 + row + sw] = bvec.z; Ws[(kq*4+3)*92 + row + sw] = bvec.w;
        }
        __syncthreads();
        #pragma unroll 4
        for (int k = 0; k < 48; k++){
            int sw = 4*((k>>2) & 7);
            float4 a  = *(const float4*)&As[k*92 + 4*lr + sw];
            float4 b0 = *(const float4*)&Ws[k*92 + 8*nr + sw];
            float4 b1 = *(const float4*)&Ws[k*92 + 8*nr + 4 + sw];
            ull bu[4] = { pack2(b0.x, b0.y), pack2(b0.z, b0.w),
                          pack2(b1.x, b1.y), pack2(b1.z, b1.w) };
            ull pa[4] = { splat2(a.x), splat2(a.y), splat2(a.z), splat2(a.w) };
            #pragma unroll
            for (int i = 0; i < 4; i++)
                #pragma unroll
                for (int j = 0; j < 4; j++)
                    acc2[i][j] = fma2(pa[i], bu[j], acc2[i][j]);
        }
    }
    #pragma unroll
    for (int i = 0; i < 4; i++){
        float2 p0 = unpack2(acc2[i][0]), p1 = unpack2(acc2[i][1]);
        float2 p2 = unpack2(acc2[i][2]), p3 = unpack2(acc2[i][3]);
        float* dst = &g_xz[(size_t)(m0 + 4*lr + i)*E2 + n0 + 8*nr];
        *(float4*)dst       = make_float4(p0.x, p0.y, p1.x, p1.y);
        *(float4*)(dst + 4) = make_float4(p2.x, p2.y, p3.x, p3.y);
    }
}

// ---------------- K3: causal conv4 + SiLU (4 t-chunks of 128) -----------------
__global__ void conv_kernel(const float* __restrict__ cw0, const float* __restrict__ cb0,
                            const float* __restrict__ cw1, const float* __restrict__ cb1,
                            const float* __restrict__ cw2, const float* __restrict__ cb2){
    int d   = threadIdx.x;            // 0..191
    int tc  = blockIdx.x;             // 0..3
    int b   = blockIdx.y;             // 0..63
    int br  = blockIdx.z;             // 0..2
    const float* cw = (br == 0) ? cw0 : (br == 1) ? cw1 : cw2;
    const float* cb = (br == 0) ? cb0 : (br == 1) ? cb1 : cb2;
    float w0 = cw[d*4+0], w1 = cw[d*4+1], w2 = cw[d*4+2], w3 = cw[d*4+3];
    float bias = cb[d];
    const float* xb = g_xz + (size_t)b*LSEQ*E2 + d;
    float* ub = g_u[br] + (size_t)(b*LSEQ)*DI + d;
    int t0 = tc*128;
    float x1 = 0.f, x2 = 0.f, x3 = 0.f;
    if (t0 >= 1) x1 = xb[perm_idx(br, t0-1)*E2];
    if (t0 >= 2) x2 = xb[perm_idx(br, t0-2)*E2];
    if (t0 >= 3) x3 = xb[perm_idx(br, t0-3)*E2];
    float pf[8];
    #pragma unroll
    for (int j = 0; j < 8; j++) pf[j] = xb[perm_idx(br, t0+j)*E2];
    #pragma unroll 8
    for (int i = 0; i < 128; i++){
        int t = t0 + i;
        float xv = pf[i & 7];
        int tn = t + 8;
        if (tn < (tc+1)*128 + 8 && tn < LSEQ) pf[i & 7] = xb[perm_idx(br, tn)*E2];
        float acc = bias;
        acc = fmaf(w0, x3, acc);
        acc = fmaf(w1, x2, acc);
        acc = fmaf(w2, x1, acc);
        acc = fmaf(w3, xv, acc);
        ub[t*DI] = siluf(acc);
        x3 = x2; x2 = x1; x1 = xv;
    }
}

// ---------------- K4: x_dbl GEMM + dt/B/C out (f32x2, 8m x 10r, M-tile 256) ---
#define XDBL_SMEM ((2880 + 32*316)*4)   // 51968 B
__global__ void xdbl_kernel(const float* __restrict__ xp0,
                            const float* __restrict__ xp1,
                            const float* __restrict__ xp2){
    extern __shared__ float sm[];
    float* ws2 = sm;                  // float2[32][45]
    float* us  = sm + 2880;           // [32][316]
    float* xds = sm;                  // overlay [256][41]
    int tid = threadIdx.x;            // 128
    int br  = blockIdx.y;
    int m0  = blockIdx.x * 256;
    const float* xpw = (br == 0) ? xp0 : (br == 1) ? xp1 : xp2;
    const float* gu = g_u[br];
    int mg = tid & 31;      // 8 m rows (4 pairs)
    int rg = tid >> 5;      // 10 r cols (0..3)
    ull acc2[4][10];
    #pragma unroll
    for (int i = 0; i < 4; i++)
        #pragma unroll
        for (int j = 0; j < 10; j++) acc2[i][j] = 0ull;
    for (int kk = 0; kk < 192; kk += 32){
        __syncthreads();
        for (int f = tid; f < 304; f += 128){
            int r = f >> 3, k4 = f & 7;
            float4 v = *(const float4*)&xpw[r*192 + kk + 4*k4];
            *(ull*)&ws2[((4*k4+0)*45 + r)*2] = pack2(v.x, v.x);
            *(ull*)&ws2[((4*k4+1)*45 + r)*2] = pack2(v.y, v.y);
            *(ull*)&ws2[((4*k4+2)*45 + r)*2] = pack2(v.z, v.z);
            *(ull*)&ws2[((4*k4+3)*45 + r)*2] = pack2(v.w, v.w);
        }
        for (int f = tid; f < 224; f += 128){
            int k = f / 7, r = 38 + f % 7;
            *(ull*)&ws2[(k*45 + r)*2] = 0ull;
        }
        for (int f = tid; f < 2048; f += 128){
            int m = f >> 3, k4 = f & 7;
            float4 v = *(const float4*)&gu[(size_t)(m0+m)*192 + kk + 4*k4];
            int col = m + 4*k4 + 4*((m >> 5) & 7);
            us[(4*k4+0)*316 + col] = v.x;
            us[(4*k4+1)*316 + col] = v.y;
            us[(4*k4+2)*316 + col] = v.z;
            us[(4*k4+3)*316 + col] = v.w;
        }
        __syncthreads();
        #pragma unroll 4
        for (int k = 0; k < 32; k++){
            int ac = 8*mg + 4*((mg>>2) & 7) + 4*(k >> 2);
            float4 a0 = *(const float4*)&us[k*316 + ac];
            float4 a1 = *(const float4*)&us[k*316 + ac + 4];
            ull au[4] = { pack2(a0.x, a0.y), pack2(a0.z, a0.w),
                          pack2(a1.x, a1.y), pack2(a1.z, a1.w) };
            const ull* wp = (const ull*)&ws2[k*90];
            #pragma unroll
            for (int j = 0; j < 10; j++){
                ull wv = wp[10*rg + j];
                #pragma unroll
                for (int i = 0; i < 4; i++)
                    acc2[i][j] = fma2(au[i], wv, acc2[i][j]);
            }
        }
    }
    __syncthreads();
    #pragma unroll
    for (int i = 0; i < 4; i++)
        #pragma unroll
        for (int j = 0; j < 10; j++){
            float2 p = unpack2(acc2[i][j]);
            xds[(8*mg + 2*i    )*41 + 10*rg + j] = p.x;
            xds[(8*mg + 2*i + 1)*41 + 10*rg + j] = p.y;
        }
    __syncthreads();
    {
        float* gdt = g_dt[br] + (size_t)m0*6;
        for (int f = tid; f < 1536; f += 128){
            int m = f / 6, r = f % 6;
            gdt[f] = xds[m*41 + r];
        }
    }
    float* gB = g_Bm[br];
    float* gC = g_Cm[br];
    for (int f = tid; f < 8192; f += 128){
        int m = f >> 5, j = f & 31;
        float v = xds[m*41 + 6 + j];
        if (j < 16) gB[(size_t)(m0+m)*DS + j]      = v;
        else        gC[(size_t)(m0+m)*DS + (j-16)] = v;
    }
}

// ---------------- K4b: delta kernel (streaming, high occupancy) ---------------
__global__ void delta_kernel(const float* __restrict__ dw0, const float* __restrict__ db0,
                             const float* __restrict__ dw1, const float* __restrict__ db1,
                             const float* __restrict__ dw2, const float* __restrict__ db2){
    __shared__ float sdt[64*6];
    int d  = threadIdx.x;             // 192
    int br = blockIdx.y;
    int m0 = blockIdx.x * 64;
    const float* dtw = (br == 0) ? dw0 : (br == 1) ? dw1 : dw2;
    const float* dtb = (br == 0) ? db0 : (br == 1) ? db1 : db2;
    {
        const float* src = g_dt[br] + (size_t)m0*6;
        for (int f = d; f < 384; f += 192) sdt[f] = src[f];
    }
    float dwr[6];
    #pragma unroll
    for (int r = 0; r < 6; r++) dwr[r] = dtw[d*6 + r];
    float db_ = dtb[d];
    float* gD = g_delta[br] + (size_t)m0*DI + d;
    __syncthreads();
    #pragma unroll 4
    for (int m = 0; m < 64; m++){
        float acc = db_;
        #pragma unroll
        for (int r = 0; r < 6; r++)
            acc = fmaf(sdt[m*6 + r], dwr[r], acc);
        gD[m*DI] = softplusf(acc);
    }
}

// ---------------- K5: selective scan (chunked smem, f32x2 power tree) ---------
__global__ void scan_kernel(const float* __restrict__ Al0, const float* __restrict__ Dp0,
                            const float* __restrict__ Al1, const float* __restrict__ Dp1,
                            const float* __restrict__ Al2, const float* __restrict__ Dp2){
    __shared__ float sd[16*96];
    __shared__ float su[16*96];
    __shared__ __align__(16) float sB[16*16];
    __shared__ __align__(16) float sC[16*16];
    int tid  = threadIdx.x;           // 0..95
    int b    = blockIdx.x;
    int half = blockIdx.y;
    int br   = blockIdx.z;
    int d    = half*96 + tid;
    const float* Alog = (br == 0) ? Al0 : (br == 1) ? Al1 : Al2;
    const float* Dp   = (br == 0) ? Dp0 : (br == 1) ? Dp1 : Dp2;
    float Ar[16];
    #pragma unroll
    for (int s = 0; s < 16; s++) Ar[s] = -__expf(Alog[d*16 + s]);
    bool fast = true;
    #pragma unroll
    for (int s = 0; s < 16; s++)
        fast = fast && (fabsf(Ar[s] + (float)(s+1)) < 1e-3f*(float)(s+1));
    float Ar0 = Ar[0];
    float Dd = Dp[d];
    ull h2[8];
    #pragma unroll
    for (int s = 0; s < 8; s++) h2[s] = 0ull;
    float hs[16];
    #pragma unroll
    for (int s = 0; s < 16; s++) hs[s] = 0.f;
    const float* gdp = g_delta[br] + (size_t)(b*LSEQ)*DI + d;
    const float* gup = g_u[br]     + (size_t)(b*LSEQ)*DI + d;
    const float* gBp = g_Bm[br]    + (size_t)(b*LSEQ)*DS;
    const float* gCp = g_Cm[br]    + (size_t)(b*LSEQ)*DS;
    float* yb = g_y[br] + (size_t)(b*LSEQ)*DI + d;
    float pd[16], pu[16], pb[3], pc[3];
    #pragma unroll
    for (int i = 0; i < 16; i++){ pd[i] = gdp[i*DI]; pu[i] = gup[i*DI]; }
    #pragma unroll
    for (int i = 0; i < 3; i++){
        int idx = i*96 + tid;
        pb[i] = (idx < 256) ? gBp[idx] : 0.f;
        pc[i] = (idx < 256) ? gCp[idx] : 0.f;
    }
    for (int c = 0; c < 32; c++){
        #pragma unroll
        for (int i = 0; i < 16; i++){ sd[i*96+tid] = pd[i]; su[i*96+tid] = pu[i]; }
        #pragma unroll
        for (int i = 0; i < 3; i++){
            int idx = i*96 + tid;
            if (idx < 256){ sB[idx] = pb[i]; sC[idx] = pc[i]; }
        }
        __syncthreads();
        if (c + 1 < 32){
            size_t ofs = (size_t)(c+1)*16*DI;
            #pragma unroll
            for (int i = 0; i < 16; i++){ pd[i] = gdp[ofs + i*DI]; pu[i] = gup[ofs + i*DI]; }
            int ofb = (c+1)*256;
            #pragma unroll
            for (int i = 0; i < 3; i++){
                int idx = i*96 + tid;
                if (idx < 256){ pb[i] = gBp[ofb + idx]; pc[i] = gCp[ofb + idx]; }
            }
        }
        if (fast){
            for (int t2 = 0; t2 < 16; t2++){
                float delta = sd[t2*96 + tid];
                float u     = su[t2*96 + tid];
                float du    = delta * u;
                float q  = __expf(delta * Ar0);
                float q2 = q*q;
                ull v0 = pack2(q, q2);
                ull s2 = pack2(q2, q2);
                ull v1 = mul2(v0, s2);
                float q4 = unpack2(v1).y;
                ull s4 = pack2(q4, q4);
                ull v2 = mul2(v0, s4);
                ull v3 = mul2(v1, s4);
                float q8 = unpack2(v3).y;
                ull s8 = pack2(q8, q8);
                ull pw[8] = {v0, v1, v2, v3,
                             mul2(v0, s8), mul2(v1, s8), mul2(v2, s8), mul2(v3, s8)};
                ull du2 = pack2(du, du);
                const ulonglong2* B2 = (const ulonglong2*)(sB + t2*16);
                const ulonglong2* C2 = (const ulonglong2*)(sC + t2*16);
                ull y2 = 0ull;
                #pragma unroll
                for (int i = 0; i < 4; i++){
                    ulonglong2 Bv = B2[i];
                    ulonglong2 Cv = C2[i];
                    h2[2*i]   = fma2(h2[2*i],   pw[2*i],   mul2(Bv.x, du2));
                    y2 = fma2(h2[2*i], Cv.x, y2);
                    h2[2*i+1] = fma2(h2[2*i+1], pw[2*i+1], mul2(Bv.y, du2));
                    y2 = fma2(h2[2*i+1], Cv.y, y2);
                }
                float2 yy = unpack2(y2);
                int t = c*16 + t2;
                yb[perm_idx(br, t)*DI] = fmaf(Dd, u, yy.x + yy.y);
            }
        } else {
            for (int t2 = 0; t2 < 16; t2++){
                float delta = sd[t2*96 + tid];
                float u     = su[t2*96 + tid];
                float du    = delta * u;
                float y = 0.f;
                #pragma unroll
                for (int s = 0; s < 16; s++){
                    float dA = __expf(delta * Ar[s]);
                    hs[s] = fmaf(hs[s], dA, du * sB[t2*16 + s]);
                    y     = fmaf(hs[s], sC[t2*16 + s], y);
                }
                int t = c*16 + t2;
                yb[perm_idx(br, t)*DI] = fmaf(Dd, u, y);
            }
        }
        __syncthreads();
    }
}

// ---------------- K6: combine*silu(z) + out_proj (M-tile 128, 256 thr) --------
#define OUTP_SMEM (128*100*4)    // 51200 B (Cs overlay >= mainloop 39424 B)
__global__ void __launch_bounds__(256)
outproj_kernel(const float* __restrict__ W,
               const float* __restrict__ x,
               float* __restrict__ out){
    extern __shared__ float sm2[];
    float* As  = sm2;                 // [32][184]
    float* Ws2 = sm2 + 32*184;        // [32][124]
    float* Cs  = sm2;                 // epilogue overlay [128][100]
    int tid = threadIdx.x;            // 256
    int m0 = blockIdx.x * 128;
    int mg = tid & 31;                // 4 m rows
    int ng = tid >> 5;                // 0..7, 12 c cols (6 pairs)
    ull acc2[4][6];
    #pragma unroll
    for (int i = 0; i < 4; i++)
        #pragma unroll
        for (int j = 0; j < 6; j++) acc2[i][j] = 0ull;
    for (int kk = 0; kk < 192; kk += 32){
        __syncthreads();
        for (int f = tid; f < 1024; f += 256){
            int m = f >> 3, k4 = f & 7;
            size_t mi = (size_t)(m0+m)*DI + kk + 4*k4;
            float4 y0 = *(const float4*)&g_y[0][mi];
            float4 y1 = *(const float4*)&g_y[1][mi];
            float4 y2 = *(const float4*)&g_y[2][mi];
            float4 z  = *(const float4*)&g_xz[(size_t)(m0+m)*E2 + DI + kk + 4*k4];
            int col = m + 4*k4;
            As[(4*k4+0)*184 + col] = (y0.x+y1.x+y2.x)*siluf(z.x);
            As[(4*k4+1)*184 + col] = (y0.y+y1.y+y2.y)*siluf(z.y);
            As[(4*k4+2)*184 + col] = (y0.z+y1.z+y2.z)*siluf(z.z);
            As[(4*k4+3)*184 + col] = (y0.w+y1.w+y2.w)*siluf(z.w);
        }
        for (int f = tid; f < 768; f += 256){
            int cc = f >> 3, k4 = f & 7;
            float4 wv = *(const float4*)&W[cc*DI + kk + 4*k4];
            int col = cc + 4*k4;
            Ws2[(4*k4+0)*124 + col] = wv.x;
            Ws2[(4*k4+1)*124 + col] = wv.y;
            Ws2[(4*k4+2)*124 + col] = wv.z;
            Ws2[(4*k4+3)*124 + col] = wv.w;
        }
        __syncthreads();
        #pragma unroll 4
        for (int k = 0; k < 32; k++){
            int sw = 4*(k >> 2);
            float4 a = *(const float4*)&As[k*184 + 4*mg + sw];
            ull pa[4] = { splat2(a.x), splat2(a.y), splat2(a.z), splat2(a.w) };
            float4 b0 = *(const float4*)&Ws2[k*124 + 12*ng + sw];
            float4 b1 = *(const float4*)&Ws2[k*124 + 12*ng + 4 + sw];
            float4 b2 = *(const float4*)&Ws2[k*124 + 12*ng + 8 + sw];
            ull bu[6] = { pack2(b0.x,b0.y), pack2(b0.z,b0.w),
                          pack2(b1.x,b1.y), pack2(b1.z,b1.w),
                          pack2(b2.x,b2.y), pack2(b2.z,b2.w) };
            #pragma unroll
            for (int i = 0; i < 4; i++)
                #pragma unroll
                for (int j = 0; j < 6; j++)
                    acc2[i][j] = fma2(pa[i], bu[j], acc2[i][j]);
        }
    }
    __syncthreads();
    #pragma unroll
    for (int i = 0; i < 4; i++){
        float2 p0 = unpack2(acc2[i][0]), p1 = unpack2(acc2[i][1]);
        float2 p2 = unpack2(acc2[i][2]), p3 = unpack2(acc2[i][3]);
        float2 p4 = unpack2(acc2[i][4]), p5 = unpack2(acc2[i][5]);
        float* dst = &Cs[(4*mg+i)*100 + 12*ng];
        *(float4*)(dst    ) = make_float4(p0.x, p0.y, p1.x, p1.y);
        *(float4*)(dst + 4) = make_float4(p2.x, p2.y, p3.x, p3.y);
        *(float4*)(dst + 8) = make_float4(p4.x, p4.y, p5.x, p5.y);
    }
    __syncthreads();
    for (int f = tid; f < 128*96; f += 256){
        int cc = f >> 7, m = f & 127;
        int M = m0 + m;
        int b = M >> 9, l = M & 511;
        int hb = b >> 4, wb = (b >> 2) & 3, db = b & 3;
        int lh = l >> 6, lw = (l >> 3) & 7, ld = l & 7;
        int sp = (hb*8+lh)*1024 + (wb*8+lw)*32 + (db*8+ld);
        int oi = cc*NSPAT + sp;
        out[oi] = Cs[m*100 + cc] + x[oi];
    }
}

// ---------------- K7/K8/K9: ECA ----------------------------------------------
__global__ void mean_kernel(const float* __restrict__ out){
    __shared__ float red[256];
    int c = blockIdx.x;
    const float4* p = (const float4*)(out + (size_t)c*NSPAT);
    float s = 0.f;
    for (int i = threadIdx.x; i < NSPAT/4; i += 256){
        float4 v = p[i];
        s += (v.x + v.y) + (v.z + v.w);
    }
    red[threadIdx.x] = s; __syncthreads();
    for (int st = 128; st > 0; st >>= 1){
        if (threadIdx.x < st) red[threadIdx.x] += red[threadIdx.x + st];
        __syncthreads();
    }
    if (threadIdx.x == 0) g_mean[c] = red[0] * (1.f/NSPAT);
}

__global__ void gate_kernel(const float* __restrict__ ew){
    int c = threadIdx.x;
    if (c < CM){
        float m0 = (c > 0)    ? g_mean[c-1] : 0.f;
        float m1 = g_mean[c];
        float m2 = (c < CM-1) ? g_mean[c+1] : 0.f;
        float v = ew[0]*m0 + ew[1]*m1 + ew[2]*m2;
        g_gate[c] = 1.f / (1.f + __expf(-v));
    }
}

__global__ void scale_kernel(float* __restrict__ out){
    int i = blockIdx.x*256 + threadIdx.x;
    float g = g_gate[i >> 13];
    float4* p = (float4*)out;
    float4 v = p[i];
    v.x *= g; v.y *= g; v.z *= g; v.w *= g;
    p[i] = v;
}

// -----------------------------------------------------------------------------
extern "C" void kernel_launch(void* const* d_in, const int* in_sizes, int n_in,
                              void* d_out, int out_size){
    const float* x   = (const float*)d_in[0];
    const float* lnw = (const float*)d_in[1];
    const float* lnb = (const float*)d_in[2];
    const float* ipw = (const float*)d_in[3];
    const float* opw = (const float*)d_in[4];
    int base, eca_idx;
    if (in_sizes[5] == 3) { eca_idx = 5;  base = 6; }
    else                  { base = 5;     eca_idx = 26; }
    const float* ecw = (const float*)d_in[eca_idx];
    const float *cw[3], *cb[3], *xp[3], *dw[3], *db[3], *Al[3], *Dp[3];
    for (int br = 0; br < 3; br++){
        const int o = base + 7*br;
        cw[br] = (const float*)d_in[o+0];
        cb[br] = (const float*)d_in[o+1];
        xp[br] = (const float*)d_in[o+2];
        dw[br] = (const float*)d_in[o+3];
        db[br] = (const float*)d_in[o+4];
        Al[br] = (const float*)d_in[o+5];
        Dp[br] = (const float*)d_in[o+6];
    }
    float* out = (float*)d_out;

    cudaFuncSetAttribute(ln_kernel,      cudaFuncAttributeMaxDynamicSharedMemorySize, 96*129*4);
    cudaFuncSetAttribute(xdbl_kernel,    cudaFuncAttributeMaxDynamicSharedMemorySize, XDBL_SMEM);
    cudaFuncSetAttribute(outproj_kernel, cudaFuncAttributeMaxDynamicSharedMemorySize, OUTP_SMEM);

    ln_kernel<<<NSPAT/128, 128, 96*129*4>>>(x, lnw, lnb);
    { dim3 g(NPOS/64, E2/64); inproj_kernel<<<g, 128>>>(ipw); }
    { dim3 g(4, WNB, 3); conv_kernel<<<g, DI>>>(cw[0],cb[0],cw[1],cb[1],cw[2],cb[2]); }
    { dim3 g(NPOS/256, 3); xdbl_kernel<<<g, 128, XDBL_SMEM>>>(xp[0], xp[1], xp[2]); }
    { dim3 g(NPOS/64, 3);  delta_kernel<<<g, 192>>>(dw[0],db[0],dw[1],db[1],dw[2],db[2]); }
    { dim3 g(WNB, 2, 3); scan_kernel<<<g, 96>>>(Al[0],Dp[0],Al[1],Dp[1],Al[2],Dp[2]); }
    outproj_kernel<<<NPOS/128, 256, OUTP_SMEM>>>(opw, x, out);
    mean_kernel<<<CM, 256>>>(out);
    gate_kernel<<<1, 128>>>(ecw);
    scale_kernel<<<(CM*NSPAT/4)/256, 256>>>(out);
    (void)n_in; (void)out_size;
}